// round 9
// baseline (speedup 1.0000x reference)
#include <cuda_runtime.h>
#include <cuda.h>
#include <cuda_fp16.h>
#include <cstdint>

#define TOKENS 8192
#define IN_F   4096
#define OUT_F  4096

#if defined(__CUDA_ARCH_FEAT_SM103_ALL) || defined(__CUDA_ARCH_FEAT_SM100_ALL) || defined(__CUDA_ARCH_FEAT_SM101_ALL)
#define HAS_TC 1
#else
#define HAS_TC 0
#endif

// ---------------- scratch (device globals: no allocations allowed) ----------
__device__ __half  g_xh[(size_t)TOKENS * IN_F];          // FWHT(x), fp16
__device__ uint8_t g_codes[(size_t)OUT_F * (IN_F / 2)];  // codes repacked to u8

// ---------------- small PTX helpers ----------------------------------------
__device__ __forceinline__ uint32_t smem_u32(const void* p) {
    uint32_t a;
    asm("{ .reg .u64 t; cvta.to.shared.u64 t, %1; cvt.u32.u64 %0, t; }" : "=r"(a) : "l"(p));
    return a;
}
__device__ __forceinline__ void mbar_init(uint32_t a, uint32_t cnt) {
    asm volatile("mbarrier.init.shared.b64 [%0], %1;" :: "r"(a), "r"(cnt) : "memory");
}
__device__ __forceinline__ void mbar_expect(uint32_t a, uint32_t bytes) {
    asm volatile("mbarrier.arrive.expect_tx.shared.b64 _, [%0], %1;" :: "r"(a), "r"(bytes) : "memory");
}
__device__ __forceinline__ void mbar_arrive(uint32_t a) {
    asm volatile("mbarrier.arrive.shared.b64 _, [%0];" :: "r"(a) : "memory");
}
__device__ __forceinline__ void mbar_wait(uint32_t a, uint32_t parity) {
    asm volatile(
        "{\n\t.reg .pred P;\n\t"
        "WAITLP_%=:\n\t"
        "mbarrier.try_wait.parity.shared::cta.b64 P, [%0], %1, 0x989680;\n\t"
        "@!P bra WAITLP_%=;\n\t"
        "}" :: "r"(a), "r"(parity) : "memory");
}
__device__ __forceinline__ void tma2d(uint32_t dst, const void* map, int cx, int cy, uint32_t bar) {
    asm volatile(
        "cp.async.bulk.tensor.2d.shared::cta.global.tile.mbarrier::complete_tx::bytes "
        "[%0], [%1, {%2, %3}], [%4];"
        :: "r"(dst), "l"(map), "r"(cx), "r"(cy), "r"(bar) : "memory");
}

// ---------------- kernel 1: blockwise FWHT of x (block = 1024) --------------
__device__ __forceinline__ void r8(float v[8]) {
    float a;
    a = v[0]; v[0] = a + v[1]; v[1] = a - v[1];
    a = v[2]; v[2] = a + v[3]; v[3] = a - v[3];
    a = v[4]; v[4] = a + v[5]; v[5] = a - v[5];
    a = v[6]; v[6] = a + v[7]; v[7] = a - v[7];
    a = v[0]; v[0] = a + v[2]; v[2] = a - v[2];
    a = v[1]; v[1] = a + v[3]; v[3] = a - v[3];
    a = v[4]; v[4] = a + v[6]; v[6] = a - v[6];
    a = v[5]; v[5] = a + v[7]; v[7] = a - v[7];
    a = v[0]; v[0] = a + v[4]; v[4] = a - v[4];
    a = v[1]; v[1] = a + v[5]; v[5] = a - v[5];
    a = v[2]; v[2] = a + v[6]; v[6] = a - v[6];
    a = v[3]; v[3] = a + v[7]; v[7] = a - v[7];
}

__global__ void __launch_bounds__(128) fwht_kernel(const float* __restrict__ x,
                                                   __half* __restrict__ xh) {
    __shared__ float s[1024];
    size_t base = (size_t)blockIdx.x * 1024;
    int t = threadIdx.x;
    int lane = t & 31;
    float v[8];
#pragma unroll
    for (int j = 0; j < 8; j++) v[j] = x[base + t + 128 * j];
    r8(v);  // index bits 7,8,9
#pragma unroll
    for (int j = 0; j < 8; j++) s[t + 128 * j] = v[j];
    __syncthreads();
    float4 p0 = reinterpret_cast<const float4*>(s)[2 * t];
    float4 p1 = reinterpret_cast<const float4*>(s)[2 * t + 1];
    v[0] = p0.x; v[1] = p0.y; v[2] = p0.z; v[3] = p0.w;
    v[4] = p1.x; v[5] = p1.y; v[6] = p1.z; v[7] = p1.w;
    r8(v);  // index bits 0,1,2
#pragma unroll
    for (int m = 1; m <= 8; m <<= 1) {  // index bits 3..6
#pragma unroll
        for (int q = 0; q < 8; q++) {
            float p = __shfl_xor_sync(0xffffffffu, v[q], m);
            v[q] = (lane & m) ? (p - v[q]) : (v[q] + p);
        }
    }
    __half2 h[4];
#pragma unroll
    for (int q = 0; q < 4; q++)
        h[q] = __floats2half2_rn(v[2 * q] * 0.03125f, v[2 * q + 1] * 0.03125f);
    *reinterpret_cast<uint4*>(xh + base + 8 * t) = *reinterpret_cast<uint4*>(h);
}

// ---------------- kernel 2: repack codes int32 -> uint8 ---------------------
__global__ void __launch_bounds__(256) repack_kernel(const int* __restrict__ codes,
                                                     uchar4* __restrict__ out) {
    int i = blockIdx.x * 256 + threadIdx.x;   // handles 4 codes
    uint4 v = reinterpret_cast<const uint4*>(codes)[i];
    out[i] = make_uchar4((uint8_t)v.x, (uint8_t)v.y, (uint8_t)v.z, (uint8_t)v.w);
}

// ---------------- kernel 3: fused dequant + fp16 GEMM ------------------------
// out = xh @ W^T + bias, W dequantized in-kernel from u8 codes + smem LUT.
// BM=256 x BN=256, BK=64 fp16. A via TMA (SW128); B built by 256 threads
// (1 row each) into the identical SW128 layout. Two M=128 MMAs per K-chunk
// into TMEM cols 0-255 / 256-511.
#define BM 256
#define BN 256
#define BK 64
#define STAGES 3
#define KITERS (IN_F / BK)            // 64
#define A_ST (BM * 128)               // 32 KB per stage
#define B_ST (BN * 128)               // 32 KB per stage
#define LUT_SM 512                    // 256 x half2 = 1 KB (512..1536)
#define SMA0 2048
#define SMB0 (SMA0 + STAGES * A_ST)
#define SMEM_BYTES (SMB0 + STAGES * B_ST)   // 198656
// barriers: fullA / bready / empty per stage + done
#define FULLA(s) (16 + 48 * (s))
#define BRDY(s)  (32 + 48 * (s))
#define EMPT(s)  (48 + 48 * (s))
#define MB_DONE  160
#define IDESC 0x8400010u              // F32 acc, f16 a/b, N=256, M=128

__global__ void __launch_bounds__(256, 1) gemm_kernel(
    const __grid_constant__ CUtensorMap tma_a,
    const float* __restrict__ grid,
    const float* __restrict__ scales,
    const float* __restrict__ bias,
    float* __restrict__ out) {
    extern __shared__ char smem[];
    uint32_t sb = smem_u32(smem);
    int tid = threadIdx.x;
    int wid = tid >> 5, lane = tid & 31;
    int n0 = blockIdx.x * BN;
    int m0 = blockIdx.y * BM;

#if HAS_TC
    // ================= tcgen05 path =================
    if (wid == 0) {
        asm volatile("tcgen05.alloc.cta_group::1.sync.aligned.shared::cta.b32 [%0], %1;"
                     :: "r"(sb), "r"(512u) : "memory");
        asm volatile("tcgen05.relinquish_alloc_permit.cta_group::1.sync.aligned;");
    }
    if (tid == 0) {
        for (int s = 0; s < STAGES; s++) {
            mbar_init(sb + FULLA(s), 1);
            mbar_init(sb + BRDY(s), 256);
            mbar_init(sb + EMPT(s), 1);
        }
        mbar_init(sb + MB_DONE, 1);
    }
    // LUT: grid codebook as half2 (scale applied per-row later)
    {
        float2 gv = reinterpret_cast<const float2*>(grid)[tid];
        reinterpret_cast<__half2*>(smem + LUT_SM)[tid] = __floats2half2_rn(gv.x, gv.y);
    }
    __syncthreads();
    uint32_t tmem;
    asm volatile("ld.shared.b32 %0, [%1];" : "=r"(tmem) : "r"(sb));

    // per-thread row state (thread t owns B row n0+t)
    const uint8_t* crow = g_codes + (size_t)(n0 + tid) * (IN_F / 2);
    float4 s4 = *reinterpret_cast<const float4*>(scales + (size_t)(n0 + tid) * 4);
    const __half2* lut = reinterpret_cast<const __half2*>(smem + LUT_SM);

    int s = 0, phE = 1, phF = 0;
    for (int it = 0; it < KITERS; ++it) {
        mbar_wait(sb + EMPT(s), (uint32_t)phE);
        if (tid == 0) {
            mbar_expect(sb + FULLA(s), A_ST);
            tma2d(sb + SMA0 + s * A_ST, &tma_a, it * BK, m0, sb + FULLA(s));
        }
        // ---- dequant: 32 codes -> 64 fp16 -> row tid of B[s] (SW128) ----
        {
            const uint4* cp = reinterpret_cast<const uint4*>(crow + it * (BK / 2));
            uint4 c0 = cp[0], c1 = cp[1];
            int sidx = it >> 4;
            float sc = (sidx < 2) ? (sidx == 0 ? s4.x : s4.y) : (sidx == 2 ? s4.z : s4.w);
            __half2 sch = __half2half2(__float2half_rn(sc));
            uint32_t w8[8] = {c0.x, c0.y, c0.z, c0.w, c1.x, c1.y, c1.z, c1.w};
            char* bbase = smem + SMB0 + s * B_ST;
#pragma unroll
            for (int j = 0; j < 8; j++) {
                uint32_t w = w8[j];
                __half2 p0 = __hmul2(lut[w & 0xFF], sch);
                __half2 p1 = __hmul2(lut[(w >> 8) & 0xFF], sch);
                __half2 p2 = __hmul2(lut[(w >> 16) & 0xFF], sch);
                __half2 p3 = __hmul2(lut[w >> 24], sch);
                uint32_t off = tid * 128 + j * 16;
                uint32_t sw = off ^ ((off >> 3) & 0x70);
                uint4 pk;
                pk.x = *reinterpret_cast<uint32_t*>(&p0);
                pk.y = *reinterpret_cast<uint32_t*>(&p1);
                pk.z = *reinterpret_cast<uint32_t*>(&p2);
                pk.w = *reinterpret_cast<uint32_t*>(&p3);
                *reinterpret_cast<uint4*>(bbase + sw) = pk;
            }
        }
        asm volatile("fence.proxy.async.shared::cta;" ::: "memory");
        mbar_arrive(sb + BRDY(s));

        if (tid == 32) {
            mbar_wait(sb + FULLA(s), (uint32_t)phF);
            mbar_wait(sb + BRDY(s), (uint32_t)phF);
            uint64_t ad0 = ((uint64_t)2 << 61) | (1ull << 46) | (64ull << 32) | (1ull << 16)
                         | ((uint64_t)((sb + SMA0 + s * A_ST) >> 4) & 0x3FFF);
            uint64_t ad1 = ad0 + 1024;   // +16 KB: A rows 128..255
            uint64_t bd  = ((uint64_t)2 << 61) | (1ull << 46) | (64ull << 32) | (1ull << 16)
                         | ((uint64_t)((sb + SMB0 + s * B_ST) >> 4) & 0x3FFF);
            uint32_t acc = (it > 0) ? 1u : 0u;
#pragma unroll
            for (int kk = 0; kk < 4; kk++) {       // 4 x K=16 f16 chunks (32B)
                asm volatile(
                    "{\n\t.reg .pred p;\n\t"
                    "setp.ne.u32 p, %4, 0;\n\t"
                    "tcgen05.mma.cta_group::1.kind::f16 [%0], %1, %2, %3, {%5, %5, %5, %5}, p;\n\t"
                    "}"
                    :: "r"(tmem), "l"(ad0 + kk * 2), "l"(bd + kk * 2), "r"(IDESC),
                       "r"(acc), "r"(0u) : "memory");
                asm volatile(
                    "{\n\t.reg .pred p;\n\t"
                    "setp.ne.u32 p, %4, 0;\n\t"
                    "tcgen05.mma.cta_group::1.kind::f16 [%0], %1, %2, %3, {%5, %5, %5, %5}, p;\n\t"
                    "}"
                    :: "r"(tmem + 256), "l"(ad1 + kk * 2), "l"(bd + kk * 2), "r"(IDESC),
                       "r"(acc), "r"(0u) : "memory");
                acc = 1;
            }
            asm volatile("tcgen05.commit.cta_group::1.mbarrier::arrive::one.shared::cluster.b64 [%0];"
                         :: "r"(sb + EMPT(s)) : "memory");
        }
        if (++s == STAGES) { s = 0; phE ^= 1; phF ^= 1; }
    }
    if (tid == 32) {
        asm volatile("tcgen05.commit.cta_group::1.mbarrier::arrive::one.shared::cluster.b64 [%0];"
                     :: "r"(sb + MB_DONE) : "memory");
    }

    // ---- epilogue: warps 0-3 -> rows 0-127 (tmem cols 0-255),
    //                warps 4-7 -> rows 128-255 (tmem cols 256-511) ----
    mbar_wait(sb + MB_DONE, 0u);
    asm volatile("tcgen05.fence::after_thread_sync;" ::: "memory");

    int h = wid >> 2;
    int m = m0 + h * 128 + (wid & 3) * 32 + lane;
    float* orow = out + (size_t)m * OUT_F + n0;
    const float* brow = bias + n0;
#pragma unroll 1
    for (int j = 0; j < 8; ++j) {
        uint32_t r[32];
        asm volatile("tcgen05.ld.sync.aligned.32x32b.x32.b32 "
            "{%0, %1, %2, %3, %4, %5, %6, %7, %8, %9, %10, %11, %12, %13, %14, %15, "
            "%16, %17, %18, %19, %20, %21, %22, %23, %24, %25, %26, %27, %28, %29, %30, %31}, [%32];"
            : "=r"(r[0]), "=r"(r[1]), "=r"(r[2]), "=r"(r[3]),
              "=r"(r[4]), "=r"(r[5]), "=r"(r[6]), "=r"(r[7]),
              "=r"(r[8]), "=r"(r[9]), "=r"(r[10]), "=r"(r[11]),
              "=r"(r[12]), "=r"(r[13]), "=r"(r[14]), "=r"(r[15]),
              "=r"(r[16]), "=r"(r[17]), "=r"(r[18]), "=r"(r[19]),
              "=r"(r[20]), "=r"(r[21]), "=r"(r[22]), "=r"(r[23]),
              "=r"(r[24]), "=r"(r[25]), "=r"(r[26]), "=r"(r[27]),
              "=r"(r[28]), "=r"(r[29]), "=r"(r[30]), "=r"(r[31])
            : "r"(tmem + h * 256 + j * 32));
        asm volatile("tcgen05.wait::ld.sync.aligned;" ::: "memory");
        float f[32];
#pragma unroll
        for (int c = 0; c < 32; c++) f[c] = __uint_as_float(r[c]) + __ldg(brow + j * 32 + c);
#pragma unroll
        for (int q = 0; q < 8; q++) {
            float4 o; o.x = f[4 * q]; o.y = f[4 * q + 1]; o.z = f[4 * q + 2]; o.w = f[4 * q + 3];
            reinterpret_cast<float4*>(orow + j * 32)[q] = o;
        }
    }
    __syncthreads();
    if (wid == 0) {
        asm volatile("tcgen05.dealloc.cta_group::1.sync.aligned.b32 %0, %1;"
                     :: "r"(tmem), "r"(512u));
    }
#else
    // ===== never-run fallback (family-generic PTX pass must compile) =====
    for (int oi = tid; oi < BM * BN; oi += 256) {
        int r = m0 + oi / BN;
        int c = n0 + oi % BN;
        float acc = __ldg(bias + c);
        const __half* ar = g_xh + (size_t)r * IN_F;
        const uint8_t* cr = g_codes + (size_t)c * (IN_F / 2);
        for (int k = 0; k < IN_F; k++) {
            float w = grid[cr[k >> 1] * 2 + (k & 1)] * scales[c * 4 + (k >> 10)];
            acc += __half2float(ar[k]) * w;
        }
        out[(size_t)r * OUT_F + c] = acc;
    }
#endif
}

// ---------------- host launch ------------------------------------------------
extern "C" void kernel_launch(void* const* d_in, const int* in_sizes, int n_in,
                              void* d_out, int out_size) {
    (void)in_sizes; (void)n_in; (void)out_size;
    const float* x      = (const float*)d_in[0];
    const int*   codes  = (const int*)d_in[1];
    const float* grid   = (const float*)d_in[2];
    const float* scales = (const float*)d_in[3];
    const float* bias   = (const float*)d_in[4];
    float* out = (float*)d_out;

    void* xh_ptr = nullptr; void* cd_ptr = nullptr;
    cudaGetSymbolAddress(&xh_ptr, g_xh);
    cudaGetSymbolAddress(&cd_ptr, g_codes);

    typedef CUresult (*EncodeFn)(CUtensorMap*, CUtensorMapDataType, cuuint32_t, void*,
        const cuuint64_t*, const cuuint64_t*, const cuuint32_t*, const cuuint32_t*,
        CUtensorMapInterleave, CUtensorMapSwizzle, CUtensorMapL2promotion,
        CUtensorMapFloatOOBfill);
    void* fp = nullptr;
    cudaDriverEntryPointQueryResult qr;
    cudaGetDriverEntryPoint("cuTensorMapEncodeTiled", &fp, cudaEnableDefault, &qr);
    EncodeFn enc = (EncodeFn)fp;

    CUtensorMap tma_a;
    {
        cuuint64_t dims[2]    = {IN_F, TOKENS};
        cuuint64_t strides[1] = {IN_F * 2};    // fp16
        cuuint32_t box[2]     = {BK, BM};      // 64 x 256 (128B rows)
        cuuint32_t es[2]      = {1, 1};
        enc(&tma_a, CU_TENSOR_MAP_DATA_TYPE_FLOAT16, 2, xh_ptr, dims, strides, box, es,
            CU_TENSOR_MAP_INTERLEAVE_NONE, CU_TENSOR_MAP_SWIZZLE_128B,
            CU_TENSOR_MAP_L2_PROMOTION_L2_128B, CU_TENSOR_MAP_FLOAT_OOB_FILL_NONE);
    }

    cudaFuncSetAttribute(gemm_kernel, cudaFuncAttributeMaxDynamicSharedMemorySize, SMEM_BYTES);

    fwht_kernel<<<(TOKENS * IN_F) / 1024, 128>>>(x, (__half*)xh_ptr);
    repack_kernel<<<(OUT_F * (IN_F / 2) / 4) / 256, 256>>>(codes, (uchar4*)cd_ptr);
    gemm_kernel<<<dim3(OUT_F / BN, TOKENS / BM), 256, SMEM_BYTES>>>(
        tma_a, grid, scales, bias, out);
}

// round 10
// speedup vs baseline: 1.6769x; 1.6769x over previous
#include <cuda_runtime.h>
#include <cuda.h>
#include <cuda_fp16.h>
#include <cstdint>

#define TOKENS 8192
#define IN_F   4096
#define OUT_F  4096

#if defined(__CUDA_ARCH_FEAT_SM103_ALL) || defined(__CUDA_ARCH_FEAT_SM100_ALL) || defined(__CUDA_ARCH_FEAT_SM101_ALL)
#define HAS_TC 1
#else
#define HAS_TC 0
#endif

// ---------------- scratch (device globals: no allocations allowed) ----------
__device__ __half g_xh[(size_t)TOKENS * IN_F];  // Hadamard-transformed x (fp16)
__device__ __half g_w [(size_t)OUT_F  * IN_F];  // dequantized W (fp16)

// ---------------- small PTX helpers ----------------------------------------
__device__ __forceinline__ uint32_t smem_u32(const void* p) {
    uint32_t a;
    asm("{ .reg .u64 t; cvta.to.shared.u64 t, %1; cvt.u32.u64 %0, t; }" : "=r"(a) : "l"(p));
    return a;
}
__device__ __forceinline__ void mbar_init(uint32_t a, uint32_t cnt) {
    asm volatile("mbarrier.init.shared.b64 [%0], %1;" :: "r"(a), "r"(cnt) : "memory");
}
__device__ __forceinline__ void mbar_expect(uint32_t a, uint32_t bytes) {
    asm volatile("mbarrier.arrive.expect_tx.shared.b64 _, [%0], %1;" :: "r"(a), "r"(bytes) : "memory");
}
__device__ __forceinline__ void mbar_wait(uint32_t a, uint32_t parity) {
    asm volatile(
        "{\n\t.reg .pred P;\n\t"
        "WAITLP_%=:\n\t"
        "mbarrier.try_wait.parity.shared::cta.b64 P, [%0], %1, 0x989680;\n\t"
        "@!P bra WAITLP_%=;\n\t"
        "}" :: "r"(a), "r"(parity) : "memory");
}
// arrive on the same-offset mbarrier in cluster CTA `rank0` (here always rank 0)
__device__ __forceinline__ void mbar_arrive_rank0(uint32_t local_addr) {
    asm volatile(
        "{\n\t.reg .b32 rem;\n\t"
        "mapa.shared::cluster.u32 rem, %0, 0;\n\t"
        "mbarrier.arrive.shared::cluster.b64 _, [rem];\n\t"
        "}" :: "r"(local_addr) : "memory");
}
__device__ __forceinline__ void tma2d(uint32_t dst, const void* map, int cx, int cy, uint32_t bar) {
    asm volatile(
        "cp.async.bulk.tensor.2d.shared::cta.global.tile.mbarrier::complete_tx::bytes "
        "[%0], [%1, {%2, %3}], [%4];"
        :: "r"(dst), "l"(map), "r"(cx), "r"(cy), "r"(bar) : "memory");
}

// ---------------- kernel 1: blockwise FWHT of x (block = 1024) --------------
__device__ __forceinline__ void r8(float v[8]) {
    float a;
    a = v[0]; v[0] = a + v[1]; v[1] = a - v[1];
    a = v[2]; v[2] = a + v[3]; v[3] = a - v[3];
    a = v[4]; v[4] = a + v[5]; v[5] = a - v[5];
    a = v[6]; v[6] = a + v[7]; v[7] = a - v[7];
    a = v[0]; v[0] = a + v[2]; v[2] = a - v[2];
    a = v[1]; v[1] = a + v[3]; v[3] = a - v[3];
    a = v[4]; v[4] = a + v[6]; v[6] = a - v[6];
    a = v[5]; v[5] = a + v[7]; v[7] = a - v[7];
    a = v[0]; v[0] = a + v[4]; v[4] = a - v[4];
    a = v[1]; v[1] = a + v[5]; v[5] = a - v[5];
    a = v[2]; v[2] = a + v[6]; v[6] = a - v[6];
    a = v[3]; v[3] = a + v[7]; v[7] = a - v[7];
}

__global__ void __launch_bounds__(128) fwht_kernel(const float* __restrict__ x,
                                                   __half* __restrict__ xh) {
    __shared__ float s[1024];
    size_t base = (size_t)blockIdx.x * 1024;
    int t = threadIdx.x;
    int lane = t & 31;
    float v[8];
#pragma unroll
    for (int j = 0; j < 8; j++) v[j] = x[base + t + 128 * j];
    r8(v);  // index bits 7,8,9
#pragma unroll
    for (int j = 0; j < 8; j++) s[t + 128 * j] = v[j];
    __syncthreads();
    float4 p0 = reinterpret_cast<const float4*>(s)[2 * t];
    float4 p1 = reinterpret_cast<const float4*>(s)[2 * t + 1];
    v[0] = p0.x; v[1] = p0.y; v[2] = p0.z; v[3] = p0.w;
    v[4] = p1.x; v[5] = p1.y; v[6] = p1.z; v[7] = p1.w;
    r8(v);  // index bits 0,1,2
#pragma unroll
    for (int m = 1; m <= 8; m <<= 1) {  // index bits 3..6
#pragma unroll
        for (int q = 0; q < 8; q++) {
            float p = __shfl_xor_sync(0xffffffffu, v[q], m);
            v[q] = (lane & m) ? (p - v[q]) : (v[q] + p);
        }
    }
    __half2 h[4];
#pragma unroll
    for (int q = 0; q < 4; q++)
        h[q] = __floats2half2_rn(v[2 * q] * 0.03125f, v[2 * q + 1] * 0.03125f);
    *reinterpret_cast<uint4*>(xh + base + 8 * t) = *reinterpret_cast<uint4*>(h);
}

// ---------------- kernel 2: dequantize W (fp16 out) --------------------------
__global__ void __launch_bounds__(256) dequant_kernel(const int* __restrict__ codes,
                                                      const float* __restrict__ grid,
                                                      const float* __restrict__ scales,
                                                      __half2* __restrict__ W) {
    int g = blockIdx.x * 256 + threadIdx.x;      // 0 .. OUT_F*IN_F/2-1
    int o  = g >> 11;                            // row (IN_F/2 = 2048 groups/row)
    int gi = g & 2047;
    int c = codes[g];
    float2 gv = reinterpret_cast<const float2*>(grid)[c];
    float sc = __ldg(scales + o * 4 + (gi >> 9));
    W[g] = __floats2half2_rn(gv.x * sc, gv.y * sc);
}

// ---------------- kernel 3: fp16 cg2 pair-GEMM  out = xh @ W^T + bias -------
// Cluster (2,1,1): pair computes M=256 x N=512. Per CTA (rank r = bx&1):
//   A: its 128 M-rows (16 KB/iter), same smem offset in both CTAs.
//   B: N/2 split per dispatch — dispatch d covers pair cols [d*256, d*256+256);
//      CTA r holds pair-rows d*256 + r*128 .. +128 at smem offset d*16KB.
// TMEM per CTA: 128 lanes x 512 fp32 cols (both N-halves of its rows).
#define BM 256                        // pair M
#define BN 512                        // pair N
#define BK 64
#define STAGES 4
#define KITERS (IN_F / BK)            // 64
#define A_ST (128 * 128)              // 16 KB per stage per CTA
#define B_ST (256 * 128)              // 32 KB per stage per CTA (2 x 128-row)
#define SMA0 1024
#define SMB0 (SMA0 + STAGES * A_ST)   // 66560 (1024-aligned)
#define SMEM_BYTES (SMB0 + STAGES * B_ST)   // 197632
// barriers: fullL (local tx) / pairF (count 2, used on rank 0) / empty
#define FULLL(s) (16 + 48 * (s))
#define PAIRF(s) (32 + 48 * (s))
#define EMPT(s)  (48 + 48 * (s))
#define MB_DONE  (16 + 48 * STAGES)
// idesc cg2 f16: F32 acc (1<<4), f16 a/b (0), N=256 (32<<17), M=256 (16<<24)
#define IDESC 0x10400010u

__global__ void __launch_bounds__(256, 1) __cluster_dims__(2, 1, 1)
gemm_kernel(
    const __grid_constant__ CUtensorMap tma_a,
    const __grid_constant__ CUtensorMap tma_b,
    const float* __restrict__ bias,
    float* __restrict__ out) {
    extern __shared__ char smem[];
    uint32_t sb = smem_u32(smem);
    int tid = threadIdx.x;
    int wid = tid >> 5, lane = tid & 31;
    int rank = blockIdx.x & 1;                 // rank within cg2 pair
    int n0 = (blockIdx.x >> 1) * BN;
    int m0 = blockIdx.y * BM;

#if HAS_TC
    // ================= tcgen05 cg2 path =================
    if (wid == 0) {
        asm volatile("tcgen05.alloc.cta_group::2.sync.aligned.shared::cta.b32 [%0], %1;"
                     :: "r"(sb), "r"(512u) : "memory");
        asm volatile("tcgen05.relinquish_alloc_permit.cta_group::2.sync.aligned;");
    }
    if (tid == 0) {
        for (int s = 0; s < STAGES; s++) {
            mbar_init(sb + FULLL(s), 1);
            mbar_init(sb + PAIRF(s), 2);       // both CTAs' forwarders arrive
            mbar_init(sb + EMPT(s), 1);        // cg2 multicast commit
        }
        mbar_init(sb + MB_DONE, 1);
    }
    __syncthreads();
    // barriers must be live cluster-wide before remote arrivals / commits
    asm volatile("barrier.cluster.arrive.aligned;" ::: "memory");
    asm volatile("barrier.cluster.wait.aligned;" ::: "memory");

    uint32_t tmem;
    asm volatile("ld.shared.b32 %0, [%1];" : "=r"(tmem) : "r"(sb));

    if (tid == 0) {
        // ---- TMA producer (per CTA) ----
        int s = 0, ph = 1;
        for (int it = 0; it < KITERS; ++it) {
            mbar_wait(sb + EMPT(s), (uint32_t)ph);
            mbar_expect(sb + FULLL(s), A_ST + B_ST);
            // A: this CTA's 128 M-rows
            tma2d(sb + SMA0 + s * A_ST, &tma_a, it * BK, m0 + rank * 128,
                  sb + FULLL(s));
            // B: N-dispatch 0 and 1 splits for this rank
            tma2d(sb + SMB0 + s * B_ST, &tma_b, it * BK,
                  n0 + rank * 128, sb + FULLL(s));
            tma2d(sb + SMB0 + s * B_ST + 16384, &tma_b, it * BK,
                  n0 + 256 + rank * 128, sb + FULLL(s));
            if (++s == STAGES) { s = 0; ph ^= 1; }
        }
    } else if (tid == 96) {
        // ---- forwarder: local stage full -> arrive on rank 0's pairF ----
        int s = 0, ph = 0;
        for (int it = 0; it < KITERS; ++it) {
            mbar_wait(sb + FULLL(s), (uint32_t)ph);
            mbar_arrive_rank0(sb + PAIRF(s));
            if (++s == STAGES) { s = 0; ph ^= 1; }
        }
    } else if (tid == 32 && rank == 0) {
        // ---- MMA issuer (rank 0 only) ----
        int s = 0, ph = 0;
        uint32_t acc = 0;
        for (int it = 0; it < KITERS; ++it) {
            mbar_wait(sb + PAIRF(s), (uint32_t)ph);
            uint64_t ad  = ((uint64_t)2 << 61) | (1ull << 46) | (64ull << 32) | (1ull << 16)
                         | ((uint64_t)((sb + SMA0 + s * A_ST) >> 4) & 0x3FFF);
            uint64_t bd0 = ((uint64_t)2 << 61) | (1ull << 46) | (64ull << 32) | (1ull << 16)
                         | ((uint64_t)((sb + SMB0 + s * B_ST) >> 4) & 0x3FFF);
            uint64_t bd1 = bd0 + 1024;   // +16 KB: dispatch-1 B split
#pragma unroll
            for (int kk = 0; kk < 4; kk++) {       // 4 x K=16 f16 chunks
                asm volatile(
                    "{\n\t.reg .pred p;\n\t"
                    "setp.ne.u32 p, %4, 0;\n\t"
                    "tcgen05.mma.cta_group::2.kind::f16 [%0], %1, %2, %3, "
                    "{%5, %5, %5, %5, %5, %5, %5, %5}, p;\n\t"
                    "}"
                    :: "r"(tmem), "l"(ad + kk * 2), "l"(bd0 + kk * 2), "r"(IDESC),
                       "r"(acc), "r"(0u) : "memory");
                asm volatile(
                    "{\n\t.reg .pred p;\n\t"
                    "setp.ne.u32 p, %4, 0;\n\t"
                    "tcgen05.mma.cta_group::2.kind::f16 [%0], %1, %2, %3, "
                    "{%5, %5, %5, %5, %5, %5, %5, %5}, p;\n\t"
                    "}"
                    :: "r"(tmem + 256), "l"(ad + kk * 2), "l"(bd1 + kk * 2), "r"(IDESC),
                       "r"(acc), "r"(0u) : "memory");
                acc = 1;
            }
            // release stage s in BOTH CTAs when these MMAs complete
            asm volatile(
                "tcgen05.commit.cta_group::2.mbarrier::arrive::one.shared::cluster"
                ".multicast::cluster.b64 [%0], %1;"
                :: "r"(sb + EMPT(s)), "h"((uint16_t)0x3) : "memory");
            if (++s == STAGES) { s = 0; ph ^= 1; }
        }
        asm volatile(
            "tcgen05.commit.cta_group::2.mbarrier::arrive::one.shared::cluster"
            ".multicast::cluster.b64 [%0], %1;"
            :: "r"(sb + MB_DONE), "h"((uint16_t)0x3) : "memory");
    }

    // ---- epilogue: this CTA owns 128 rows x 512 cols ----
    // warp w: rows (w&3)*32, col half h = w>>2 (tmem cols h*256..)
    mbar_wait(sb + MB_DONE, 0u);
    asm volatile("tcgen05.fence::after_thread_sync;" ::: "memory");

    int h = wid >> 2;
    int m = m0 + rank * 128 + (wid & 3) * 32 + lane;
    float* orow = out + (size_t)m * OUT_F + n0 + h * 256;
    const float* brow = bias + n0 + h * 256;
#pragma unroll 1
    for (int j = 0; j < 8; ++j) {
        uint32_t r[32];
        asm volatile("tcgen05.ld.sync.aligned.32x32b.x32.b32 "
            "{%0, %1, %2, %3, %4, %5, %6, %7, %8, %9, %10, %11, %12, %13, %14, %15, "
            "%16, %17, %18, %19, %20, %21, %22, %23, %24, %25, %26, %27, %28, %29, %30, %31}, [%32];"
            : "=r"(r[0]), "=r"(r[1]), "=r"(r[2]), "=r"(r[3]),
              "=r"(r[4]), "=r"(r[5]), "=r"(r[6]), "=r"(r[7]),
              "=r"(r[8]), "=r"(r[9]), "=r"(r[10]), "=r"(r[11]),
              "=r"(r[12]), "=r"(r[13]), "=r"(r[14]), "=r"(r[15]),
              "=r"(r[16]), "=r"(r[17]), "=r"(r[18]), "=r"(r[19]),
              "=r"(r[20]), "=r"(r[21]), "=r"(r[22]), "=r"(r[23]),
              "=r"(r[24]), "=r"(r[25]), "=r"(r[26]), "=r"(r[27]),
              "=r"(r[28]), "=r"(r[29]), "=r"(r[30]), "=r"(r[31])
            : "r"(tmem + h * 256 + j * 32));
        asm volatile("tcgen05.wait::ld.sync.aligned;" ::: "memory");
        float f[32];
#pragma unroll
        for (int c = 0; c < 32; c++) f[c] = __uint_as_float(r[c]) + __ldg(brow + j * 32 + c);
#pragma unroll
        for (int q = 0; q < 8; q++) {
            float4 o; o.x = f[4 * q]; o.y = f[4 * q + 1]; o.z = f[4 * q + 2]; o.w = f[4 * q + 3];
            reinterpret_cast<float4*>(orow + j * 32)[q] = o;
        }
    }
    __syncthreads();
    if (wid == 0) {
        asm volatile("tcgen05.dealloc.cta_group::2.sync.aligned.b32 %0, %1;"
                     :: "r"(tmem), "r"(512u));
    }
    asm volatile("barrier.cluster.arrive.aligned;" ::: "memory");
    asm volatile("barrier.cluster.wait.aligned;" ::: "memory");
#else
    // ===== never-run fallback (family-generic PTX pass must compile) =====
    for (int oi = tid; oi < 128 * BN; oi += 256) {
        int r = m0 + rank * 128 + oi / BN;
        int c = n0 + oi % BN;
        float acc = __ldg(bias + c);
        const __half* ar = g_xh + (size_t)r * IN_F;
        const __half* wr = g_w + (size_t)c * IN_F;
        for (int k = 0; k < IN_F; k++) acc += __half2float(ar[k]) * __half2float(wr[k]);
        out[(size_t)r * OUT_F + c] = acc;
    }
#endif
}

// ---------------- host launch ------------------------------------------------
extern "C" void kernel_launch(void* const* d_in, const int* in_sizes, int n_in,
                              void* d_out, int out_size) {
    (void)in_sizes; (void)n_in; (void)out_size;
    const float* x      = (const float*)d_in[0];
    const int*   codes  = (const int*)d_in[1];
    const float* grid   = (const float*)d_in[2];
    const float* scales = (const float*)d_in[3];
    const float* bias   = (const float*)d_in[4];
    float* out = (float*)d_out;

    void* xh_ptr = nullptr; void* w_ptr = nullptr;
    cudaGetSymbolAddress(&xh_ptr, g_xh);
    cudaGetSymbolAddress(&w_ptr, g_w);

    typedef CUresult (*EncodeFn)(CUtensorMap*, CUtensorMapDataType, cuuint32_t, void*,
        const cuuint64_t*, const cuuint64_t*, const cuuint32_t*, const cuuint32_t*,
        CUtensorMapInterleave, CUtensorMapSwizzle, CUtensorMapL2promotion,
        CUtensorMapFloatOOBfill);
    void* fp = nullptr;
    cudaDriverEntryPointQueryResult qr;
    cudaGetDriverEntryPoint("cuTensorMapEncodeTiled", &fp, cudaEnableDefault, &qr);
    EncodeFn enc = (EncodeFn)fp;

    CUtensorMap tma_a, tma_b;
    {
        cuuint64_t dims[2]    = {IN_F, TOKENS};
        cuuint64_t strides[1] = {IN_F * 2};    // fp16
        cuuint32_t box[2]     = {BK, 128};     // 64 x 128 (128B rows)
        cuuint32_t es[2]      = {1, 1};
        enc(&tma_a, CU_TENSOR_MAP_DATA_TYPE_FLOAT16, 2, xh_ptr, dims, strides, box, es,
            CU_TENSOR_MAP_INTERLEAVE_NONE, CU_TENSOR_MAP_SWIZZLE_128B,
            CU_TENSOR_MAP_L2_PROMOTION_L2_128B, CU_TENSOR_MAP_FLOAT_OOB_FILL_NONE);
    }
    {
        cuuint64_t dims[2]    = {IN_F, OUT_F};
        cuuint64_t strides[1] = {IN_F * 2};    // fp16
        cuuint32_t box[2]     = {BK, 128};     // 64 x 128
        cuuint32_t es[2]      = {1, 1};
        enc(&tma_b, CU_TENSOR_MAP_DATA_TYPE_FLOAT16, 2, w_ptr, dims, strides, box, es,
            CU_TENSOR_MAP_INTERLEAVE_NONE, CU_TENSOR_MAP_SWIZZLE_128B,
            CU_TENSOR_MAP_L2_PROMOTION_L2_128B, CU_TENSOR_MAP_FLOAT_OOB_FILL_NONE);
    }

    cudaFuncSetAttribute(gemm_kernel, cudaFuncAttributeMaxDynamicSharedMemorySize, SMEM_BYTES);

    fwht_kernel<<<(TOKENS * IN_F) / 1024, 128>>>(x, (__half*)xh_ptr);
    dequant_kernel<<<(OUT_F * IN_F / 2) / 256, 256>>>(codes, grid, scales, (__half2*)w_ptr);
    // grid.x = 8 N-tiles x 2 CTAs per pair; grid.y = 32 M-tiles
    gemm_kernel<<<dim3((OUT_F / BN) * 2, TOKENS / BM), 256, SMEM_BYTES>>>(
        tma_a, tma_b, bias, out);
}

// round 11
// speedup vs baseline: 1.7413x; 1.0384x over previous
#include <cuda_runtime.h>
#include <cuda.h>
#include <cuda_fp16.h>
#include <cstdint>

#define TOKENS 8192
#define IN_F   4096
#define OUT_F  4096

#if defined(__CUDA_ARCH_FEAT_SM103_ALL) || defined(__CUDA_ARCH_FEAT_SM100_ALL) || defined(__CUDA_ARCH_FEAT_SM101_ALL)
#define HAS_TC 1
#else
#define HAS_TC 0
#endif

// ---------------- scratch (device globals: no allocations allowed) ----------
__device__ __half g_xh[(size_t)TOKENS * IN_F];  // Hadamard-transformed x (fp16)
__device__ __half g_w [(size_t)OUT_F  * IN_F];  // dequantized W (fp16)

// ---------------- small PTX helpers ----------------------------------------
__device__ __forceinline__ uint32_t smem_u32(const void* p) {
    uint32_t a;
    asm("{ .reg .u64 t; cvta.to.shared.u64 t, %1; cvt.u32.u64 %0, t; }" : "=r"(a) : "l"(p));
    return a;
}
__device__ __forceinline__ void mbar_init(uint32_t a, uint32_t cnt) {
    asm volatile("mbarrier.init.shared.b64 [%0], %1;" :: "r"(a), "r"(cnt) : "memory");
}
__device__ __forceinline__ void mbar_expect(uint32_t a, uint32_t bytes) {
    asm volatile("mbarrier.arrive.expect_tx.shared.b64 _, [%0], %1;" :: "r"(a), "r"(bytes) : "memory");
}
__device__ __forceinline__ void mbar_wait(uint32_t a, uint32_t parity) {
    asm volatile(
        "{\n\t.reg .pred P;\n\t"
        "WAITLP_%=:\n\t"
        "mbarrier.try_wait.parity.shared::cta.b64 P, [%0], %1, 0x989680;\n\t"
        "@!P bra WAITLP_%=;\n\t"
        "}" :: "r"(a), "r"(parity) : "memory");
}

// ---------------- kernel 1: fused FWHT(x) + dequant(W) ----------------------
// blocks [0, NFW): FWHT, 128 threads, one 1024-block each.
// blocks [NFW, NFW+NDQ): dequant, 128 threads x 4 code-groups each.
// Both are DRAM-bound; fusing into one launch overlaps them across SMs.
#define NFW ((TOKENS * IN_F) / 1024)                 // 32768
#define NDQ ((OUT_F * (IN_F / 2)) / 512)             // 16384

__device__ __forceinline__ void r8(float v[8]) {
    float a;
    a = v[0]; v[0] = a + v[1]; v[1] = a - v[1];
    a = v[2]; v[2] = a + v[3]; v[3] = a - v[3];
    a = v[4]; v[4] = a + v[5]; v[5] = a - v[5];
    a = v[6]; v[6] = a + v[7]; v[7] = a - v[7];
    a = v[0]; v[0] = a + v[2]; v[2] = a - v[2];
    a = v[1]; v[1] = a + v[3]; v[3] = a - v[3];
    a = v[4]; v[4] = a + v[6]; v[6] = a - v[6];
    a = v[5]; v[5] = a + v[7]; v[7] = a - v[7];
    a = v[0]; v[0] = a + v[4]; v[4] = a - v[4];
    a = v[1]; v[1] = a + v[5]; v[5] = a - v[5];
    a = v[2]; v[2] = a + v[6]; v[6] = a - v[6];
    a = v[3]; v[3] = a + v[7]; v[7] = a - v[7];
}

__global__ void __launch_bounds__(128) prep_kernel(
    const float* __restrict__ x,
    const int* __restrict__ codes,
    const float* __restrict__ grid,
    const float* __restrict__ scales,
    __half* __restrict__ xh,
    __half2* __restrict__ W) {
    int t = threadIdx.x;
    if (blockIdx.x < NFW) {
        // ---- FWHT of one 1024-block ----
        // bit coverage: phase1 r8 -> bits{7,8,9}; phase2 r8 -> bits{0,1,2};
        // shfl.bfly m=1,2,4,8 -> bits{3,4,5,6}
        __shared__ float s[1024];
        size_t base = (size_t)blockIdx.x * 1024;
        int lane = t & 31;
        float v[8];
#pragma unroll
        for (int j = 0; j < 8; j++) v[j] = x[base + t + 128 * j];
        r8(v);
#pragma unroll
        for (int j = 0; j < 8; j++) s[t + 128 * j] = v[j];
        __syncthreads();
        float4 p0 = reinterpret_cast<const float4*>(s)[2 * t];
        float4 p1 = reinterpret_cast<const float4*>(s)[2 * t + 1];
        v[0] = p0.x; v[1] = p0.y; v[2] = p0.z; v[3] = p0.w;
        v[4] = p1.x; v[5] = p1.y; v[6] = p1.z; v[7] = p1.w;
        r8(v);
#pragma unroll
        for (int m = 1; m <= 8; m <<= 1) {
#pragma unroll
            for (int q = 0; q < 8; q++) {
                float p = __shfl_xor_sync(0xffffffffu, v[q], m);
                v[q] = (lane & m) ? (p - v[q]) : (v[q] + p);
            }
        }
        __half2 h[4];
#pragma unroll
        for (int q = 0; q < 4; q++)
            h[q] = __floats2half2_rn(v[2 * q] * 0.03125f, v[2 * q + 1] * 0.03125f);
        *reinterpret_cast<uint4*>(xh + base + 8 * t) = *reinterpret_cast<uint4*>(h);
    } else {
        // ---- dequant: 4 consecutive code groups per thread ----
        int g0 = (blockIdx.x - NFW) * 512 + t * 4;
        uint4 c4 = reinterpret_cast<const uint4*>(codes)[g0 >> 2];
        int o  = g0 >> 11;
        int gi = g0 & 2047;
        float sc = __ldg(scales + o * 4 + (gi >> 9));  // same for all 4 groups
        __half2 h[4];
        uint32_t cc[4] = {c4.x, c4.y, c4.z, c4.w};
#pragma unroll
        for (int j = 0; j < 4; j++) {
            float2 gv = reinterpret_cast<const float2*>(grid)[cc[j]];
            h[j] = __floats2half2_rn(gv.x * sc, gv.y * sc);
        }
        *reinterpret_cast<uint4*>(W + g0) = *reinterpret_cast<uint4*>(h);
    }
}

// ---------------- kernel 2: fp16 cg2 pair-GEMM  out = xh @ W^T + bias -------
// Cluster (2,1,1): pair computes M=256 x N=512. Per CTA (rank r = bx&1):
//   A: its 128 M-rows (16 KB/iter); B: N/2 splits of both N-dispatches.
// All TMA loads use cta_group::2 -> complete_tx lands on rank 0's full
// barrier (bit-24 cleared). Rank 0 expects 96 KB/iter, issues cg2 MMAs and
// releases both CTAs' empty barriers via multicast commit.
#define BM 256                        // pair M
#define BN 512                        // pair N
#define BK 64
#define STAGES 4
#define KITERS (IN_F / BK)            // 64
#define A_ST (128 * 128)              // 16 KB per stage per CTA
#define B_ST (256 * 128)              // 32 KB per stage per CTA (2 x 128-row)
#define SMA0 1024
#define SMB0 (SMA0 + STAGES * A_ST)
#define SMEM_BYTES (SMB0 + STAGES * B_ST)   // 197632
#define FULLL(s) (16 + 32 * (s))      // leader full (tx) barrier
#define EMPT(s)  (24 + 32 * (s))      // empty barrier (multicast commit)
#define MB_DONE  (16 + 32 * STAGES)
// idesc cg2 f16: F32 acc (1<<4), f16 a/b, N=256 (32<<17), M=256 (16<<24)
#define IDESC 0x10400010u

__global__ void __launch_bounds__(256, 1) __cluster_dims__(2, 1, 1)
gemm_kernel(
    const __grid_constant__ CUtensorMap tma_a,
    const __grid_constant__ CUtensorMap tma_b,
    const float* __restrict__ bias,
    float* __restrict__ out) {
    extern __shared__ char smem[];
    uint32_t sb = smem_u32(smem);
    int tid = threadIdx.x;
    int wid = tid >> 5, lane = tid & 31;
    int rank = blockIdx.x & 1;                 // rank within cg2 pair
    int n0 = (blockIdx.x >> 1) * BN;
    int m0 = blockIdx.y * BM;

#if HAS_TC
    // ================= tcgen05 cg2 path =================
    if (wid == 0) {
        asm volatile("tcgen05.alloc.cta_group::2.sync.aligned.shared::cta.b32 [%0], %1;"
                     :: "r"(sb), "r"(512u) : "memory");
        asm volatile("tcgen05.relinquish_alloc_permit.cta_group::2.sync.aligned;");
    }
    if (tid == 0) {
        for (int s = 0; s < STAGES; s++) {
            mbar_init(sb + FULLL(s), 1);       // leader full: 1 expect-arrive
            mbar_init(sb + EMPT(s), 1);        // cg2 multicast commit
        }
        mbar_init(sb + MB_DONE, 1);
    }
    __syncthreads();
    // barriers must be live cluster-wide before cg2 TMA / multicast commits
    asm volatile("barrier.cluster.arrive.aligned;" ::: "memory");
    asm volatile("barrier.cluster.wait.aligned;" ::: "memory");

    uint32_t tmem;
    asm volatile("ld.shared.b32 %0, [%1];" : "=r"(tmem) : "r"(sb));

    if (tid == 0) {
        // ---- TMA producer (both ranks; tx -> rank 0's FULLL) ----
        int s = 0, ph = 1;
        for (int it = 0; it < KITERS; ++it) {
            mbar_wait(sb + EMPT(s), (uint32_t)ph);
            if (rank == 0)
                mbar_expect(sb + FULLL(s), 2 * (A_ST + B_ST));
            uint32_t bar = sb + FULLL(s);
            // A: this CTA's 128 M-rows
            asm volatile(
                "{\n\t.reg .b32 lb;\n\t"
                "and.b32 lb, %4, 0xFEFFFFFF;\n\t"
                "cp.async.bulk.tensor.2d.cta_group::2.shared::cluster.global.tile"
                ".mbarrier::complete_tx::bytes [%0], [%1, {%2, %3}], [lb];\n\t}"
                :: "r"(sb + SMA0 + s * A_ST), "l"(&tma_a),
                   "r"(it * BK), "r"(m0 + rank * 128), "r"(bar) : "memory");
            // B: N-dispatch 0 and 1 splits for this rank
            asm volatile(
                "{\n\t.reg .b32 lb;\n\t"
                "and.b32 lb, %4, 0xFEFFFFFF;\n\t"
                "cp.async.bulk.tensor.2d.cta_group::2.shared::cluster.global.tile"
                ".mbarrier::complete_tx::bytes [%0], [%1, {%2, %3}], [lb];\n\t}"
                :: "r"(sb + SMB0 + s * B_ST), "l"(&tma_b),
                   "r"(it * BK), "r"(n0 + rank * 128), "r"(bar) : "memory");
            asm volatile(
                "{\n\t.reg .b32 lb;\n\t"
                "and.b32 lb, %4, 0xFEFFFFFF;\n\t"
                "cp.async.bulk.tensor.2d.cta_group::2.shared::cluster.global.tile"
                ".mbarrier::complete_tx::bytes [%0], [%1, {%2, %3}], [lb];\n\t}"
                :: "r"(sb + SMB0 + s * B_ST + 16384), "l"(&tma_b),
                   "r"(it * BK), "r"(n0 + 256 + rank * 128), "r"(bar) : "memory");
            if (++s == STAGES) { s = 0; ph ^= 1; }
        }
    } else if (tid == 32 && rank == 0) {
        // ---- MMA issuer (rank 0 only) ----
        int s = 0, ph = 0;
        uint32_t acc = 0;
        for (int it = 0; it < KITERS; ++it) {
            mbar_wait(sb + FULLL(s), (uint32_t)ph);
            uint64_t ad  = ((uint64_t)2 << 61) | (1ull << 46) | (64ull << 32) | (1ull << 16)
                         | ((uint64_t)((sb + SMA0 + s * A_ST) >> 4) & 0x3FFF);
            uint64_t bd0 = ((uint64_t)2 << 61) | (1ull << 46) | (64ull << 32) | (1ull << 16)
                         | ((uint64_t)((sb + SMB0 + s * B_ST) >> 4) & 0x3FFF);
            uint64_t bd1 = bd0 + 1024;   // +16 KB: dispatch-1 B split
#pragma unroll
            for (int kk = 0; kk < 4; kk++) {       // 4 x K=16 f16 chunks
                asm volatile(
                    "{\n\t.reg .pred p;\n\t"
                    "setp.ne.u32 p, %4, 0;\n\t"
                    "tcgen05.mma.cta_group::2.kind::f16 [%0], %1, %2, %3, "
                    "{%5, %5, %5, %5, %5, %5, %5, %5}, p;\n\t"
                    "}"
                    :: "r"(tmem), "l"(ad + kk * 2), "l"(bd0 + kk * 2), "r"(IDESC),
                       "r"(acc), "r"(0u) : "memory");
                asm volatile(
                    "{\n\t.reg .pred p;\n\t"
                    "setp.ne.u32 p, %4, 0;\n\t"
                    "tcgen05.mma.cta_group::2.kind::f16 [%0], %1, %2, %3, "
                    "{%5, %5, %5, %5, %5, %5, %5, %5}, p;\n\t"
                    "}"
                    :: "r"(tmem + 256), "l"(ad + kk * 2), "l"(bd1 + kk * 2), "r"(IDESC),
                       "r"(acc), "r"(0u) : "memory");
                acc = 1;
            }
            // release stage s in BOTH CTAs when these MMAs complete
            asm volatile(
                "tcgen05.commit.cta_group::2.mbarrier::arrive::one.shared::cluster"
                ".multicast::cluster.b64 [%0], %1;"
                :: "r"(sb + EMPT(s)), "h"((uint16_t)0x3) : "memory");
            if (++s == STAGES) { s = 0; ph ^= 1; }
        }
        asm volatile(
            "tcgen05.commit.cta_group::2.mbarrier::arrive::one.shared::cluster"
            ".multicast::cluster.b64 [%0], %1;"
            :: "r"(sb + MB_DONE), "h"((uint16_t)0x3) : "memory");
    }

    // ---- epilogue: this CTA owns 128 rows x 512 cols ----
    mbar_wait(sb + MB_DONE, 0u);
    asm volatile("tcgen05.fence::after_thread_sync;" ::: "memory");

    int h = wid >> 2;
    int m = m0 + rank * 128 + (wid & 3) * 32 + lane;
    float* orow = out + (size_t)m * OUT_F + n0 + h * 256;
    const float* brow = bias + n0 + h * 256;
#pragma unroll 1
    for (int j = 0; j < 8; ++j) {
        uint32_t r[32];
        asm volatile("tcgen05.ld.sync.aligned.32x32b.x32.b32 "
            "{%0, %1, %2, %3, %4, %5, %6, %7, %8, %9, %10, %11, %12, %13, %14, %15, "
            "%16, %17, %18, %19, %20, %21, %22, %23, %24, %25, %26, %27, %28, %29, %30, %31}, [%32];"
            : "=r"(r[0]), "=r"(r[1]), "=r"(r[2]), "=r"(r[3]),
              "=r"(r[4]), "=r"(r[5]), "=r"(r[6]), "=r"(r[7]),
              "=r"(r[8]), "=r"(r[9]), "=r"(r[10]), "=r"(r[11]),
              "=r"(r[12]), "=r"(r[13]), "=r"(r[14]), "=r"(r[15]),
              "=r"(r[16]), "=r"(r[17]), "=r"(r[18]), "=r"(r[19]),
              "=r"(r[20]), "=r"(r[21]), "=r"(r[22]), "=r"(r[23]),
              "=r"(r[24]), "=r"(r[25]), "=r"(r[26]), "=r"(r[27]),
              "=r"(r[28]), "=r"(r[29]), "=r"(r[30]), "=r"(r[31])
            : "r"(tmem + h * 256 + j * 32));
        asm volatile("tcgen05.wait::ld.sync.aligned;" ::: "memory");
        float f[32];
#pragma unroll
        for (int c = 0; c < 32; c++) f[c] = __uint_as_float(r[c]) + __ldg(brow + j * 32 + c);
#pragma unroll
        for (int q = 0; q < 8; q++) {
            float4 o; o.x = f[4 * q]; o.y = f[4 * q + 1]; o.z = f[4 * q + 2]; o.w = f[4 * q + 3];
            reinterpret_cast<float4*>(orow + j * 32)[q] = o;
        }
    }
    __syncthreads();
    if (wid == 0) {
        asm volatile("tcgen05.dealloc.cta_group::2.sync.aligned.b32 %0, %1;"
                     :: "r"(tmem), "r"(512u));
    }
    asm volatile("barrier.cluster.arrive.aligned;" ::: "memory");
    asm volatile("barrier.cluster.wait.aligned;" ::: "memory");
#else
    // ===== never-run fallback (family-generic PTX pass must compile) =====
    for (int oi = tid; oi < 128 * BN; oi += 256) {
        int r = m0 + rank * 128 + oi / BN;
        int c = n0 + oi % BN;
        float acc = __ldg(bias + c);
        const __half* ar = g_xh + (size_t)r * IN_F;
        const __half* wr = g_w + (size_t)c * IN_F;
        for (int k = 0; k < IN_F; k++) acc += __half2float(ar[k]) * __half2float(wr[k]);
        out[(size_t)r * OUT_F + c] = acc;
    }
#endif
}

// ---------------- host launch ------------------------------------------------
extern "C" void kernel_launch(void* const* d_in, const int* in_sizes, int n_in,
                              void* d_out, int out_size) {
    (void)in_sizes; (void)n_in; (void)out_size;
    const float* x      = (const float*)d_in[0];
    const int*   codes  = (const int*)d_in[1];
    const float* grid   = (const float*)d_in[2];
    const float* scales = (const float*)d_in[3];
    const float* bias   = (const float*)d_in[4];
    float* out = (float*)d_out;

    void* xh_ptr = nullptr; void* w_ptr = nullptr;
    cudaGetSymbolAddress(&xh_ptr, g_xh);
    cudaGetSymbolAddress(&w_ptr, g_w);

    typedef CUresult (*EncodeFn)(CUtensorMap*, CUtensorMapDataType, cuuint32_t, void*,
        const cuuint64_t*, const cuuint64_t*, const cuuint32_t*, const cuuint32_t*,
        CUtensorMapInterleave, CUtensorMapSwizzle, CUtensorMapL2promotion,
        CUtensorMapFloatOOBfill);
    void* fp = nullptr;
    cudaDriverEntryPointQueryResult qr;
    cudaGetDriverEntryPoint("cuTensorMapEncodeTiled", &fp, cudaEnableDefault, &qr);
    EncodeFn enc = (EncodeFn)fp;

    CUtensorMap tma_a, tma_b;
    {
        cuuint64_t dims[2]    = {IN_F, TOKENS};
        cuuint64_t strides[1] = {IN_F * 2};    // fp16
        cuuint32_t box[2]     = {BK, 128};     // 64 x 128 (128B rows)
        cuuint32_t es[2]      = {1, 1};
        enc(&tma_a, CU_TENSOR_MAP_DATA_TYPE_FLOAT16, 2, xh_ptr, dims, strides, box, es,
            CU_TENSOR_MAP_INTERLEAVE_NONE, CU_TENSOR_MAP_SWIZZLE_128B,
            CU_TENSOR_MAP_L2_PROMOTION_L2_128B, CU_TENSOR_MAP_FLOAT_OOB_FILL_NONE);
    }
    {
        cuuint64_t dims[2]    = {IN_F, OUT_F};
        cuuint64_t strides[1] = {IN_F * 2};    // fp16
        cuuint32_t box[2]     = {BK, 128};     // 64 x 128
        cuuint32_t es[2]      = {1, 1};
        enc(&tma_b, CU_TENSOR_MAP_DATA_TYPE_FLOAT16, 2, w_ptr, dims, strides, box, es,
            CU_TENSOR_MAP_INTERLEAVE_NONE, CU_TENSOR_MAP_SWIZZLE_128B,
            CU_TENSOR_MAP_L2_PROMOTION_L2_128B, CU_TENSOR_MAP_FLOAT_OOB_FILL_NONE);
    }

    cudaFuncSetAttribute(gemm_kernel, cudaFuncAttributeMaxDynamicSharedMemorySize, SMEM_BYTES);

    prep_kernel<<<NFW + NDQ, 128>>>(x, codes, grid, scales,
                                    (__half*)xh_ptr, (__half2*)w_ptr);
    // grid.x = 8 N-tiles x 2 CTAs per pair; grid.y = 32 M-tiles
    gemm_kernel<<<dim3((OUT_F / BN) * 2, TOKENS / BM), 256, SMEM_BYTES>>>(
        tma_a, tma_b, bias, out);
}